// round 11
// baseline (speedup 1.0000x reference)
#include <cuda_runtime.h>
#include <cstdint>
#include <math.h>

// Fixed shapes: x = (64, 256, 4096) fp32 -> out (64, 256, 816)
#define SEQ      4096
#define MIN_W    20
#define STRIDE   5
#define OUT_LEN  816            // (4096-20)/5 + 1
#define GROUPS   204            // 816 / 4 windows per worker thread
#define EPS      1e-8f
#define NTHREADS 256
#define GRID     888            // 148 SMs x 6 resident CTAs -> one wave

// Exact XLA GPU warp-shuffle reduction tree for the 20-element window sum
// (lanes 20..31 carry identity 0; shfl-down 16,8,4,2,1). Bitwise-pinned:
// every add is a single rn FADD, no reassociation, no FMA. The MEAN must be
// bitwise-matched to the reference: global L2 rel_err is dominated by
// near-zero-mean windows where cv = std/(mean+eps) ~ 1e7.
__device__ __forceinline__ float xla_tree20(const float* __restrict__ v)
{
    float c0 = __fadd_rn(__fadd_rn(v[0], v[16]), v[8]);
    float c1 = __fadd_rn(__fadd_rn(v[1], v[17]), v[9]);
    float c2 = __fadd_rn(__fadd_rn(v[2], v[18]), v[10]);
    float c3 = __fadd_rn(__fadd_rn(v[3], v[19]), v[11]);
    float c4 = __fadd_rn(v[4], v[12]);
    float c5 = __fadd_rn(v[5], v[13]);
    float c6 = __fadd_rn(v[6], v[14]);
    float c7 = __fadd_rn(v[7], v[15]);
    float d0 = __fadd_rn(c0, c4);
    float d1 = __fadd_rn(c1, c5);
    float d2 = __fadd_rn(c2, c6);
    float d3 = __fadd_rn(c3, c7);
    return __fadd_rn(__fadd_rn(d0, d2), __fadd_rn(d1, d3));
}

__device__ __forceinline__ float sqrt_approx(float a)
{
    float r;
    asm("sqrt.approx.f32 %0, %1;" : "=f"(r) : "f"(a));
    return r;
}

__device__ __forceinline__ void stg_cs_f4(float* p, float4 v)
{
    asm volatile("st.global.cs.v4.f32 [%0], {%1, %2, %3, %4};"
                 :: "l"(p), "f"(v.x), "f"(v.y), "f"(v.z), "f"(v.w)
                 : "memory");
}

// Fire-and-forget row load GMEM -> SMEM: 4 x cp.async.cg of 16B per thread
// (256 threads cover 16 KB), then commit as one group. No register staging,
// no issue pressure after dispatch -> overlaps fully with compute.
__device__ __forceinline__ void issue_row_load(
    const float* __restrict__ xrow, float* sbuf, int tid)
{
    const float4* src = reinterpret_cast<const float4*>(xrow) + tid;
    unsigned int dst = (unsigned int)__cvta_generic_to_shared(
        reinterpret_cast<float4*>(sbuf) + tid);
    #pragma unroll
    for (int i = 0; i < 4; ++i) {
        asm volatile("cp.async.cg.shared.global [%0], [%1], 16;"
                     :: "r"(dst + i * NTHREADS * 16),
                        "l"(src + i * NTHREADS)
                     : "memory");
    }
    asm volatile("cp.async.commit_group;" ::: "memory");
}

// Persistent double-buffered pipeline: while computing row i from buffer A,
// row i+GRID is already streaming into buffer B via cp.async. This keeps
// DRAM demand continuous instead of duty-cycling at ~75% (the measured
// plateau of all phase-alternating variants).
__global__ __launch_bounds__(NTHREADS) void tscv_kernel(
    const float* __restrict__ x,
    float*       __restrict__ out,
    int nrows)
{
    __shared__ float buf[2][SEQ];

    const int tid = threadIdx.x;

    int row = blockIdx.x;
    if (row >= nrows) return;

    issue_row_load(x + (size_t)row * SEQ, buf[0], tid);

    int stage = 0;
    for (; row < nrows; row += GRID, stage ^= 1) {
        const int nxt = row + GRID;
        if (nxt < nrows) {
            issue_row_load(x + (size_t)nxt * SEQ, buf[stage ^ 1], tid);
            asm volatile("cp.async.wait_group 1;" ::: "memory");
        } else {
            asm volatile("cp.async.wait_group 0;" ::: "memory");
        }
        __syncthreads();

        if (tid < GROUPS) {
            const float* rowp = buf[stage];

            // 9 conflict-free LDS.128 (lane stride 80B = 5 x 16B units, odd
            // -> all 32 banks covered once per phase).
            float v[36];
            const float4* row4 =
                reinterpret_cast<const float4*>(rowp + MIN_W * tid);
            #pragma unroll
            for (int i = 0; i < 9; ++i) {
                const float4 t = row4[i];
                v[4 * i + 0] = t.x;
                v[4 * i + 1] = t.y;
                v[4 * i + 2] = t.z;
                v[4 * i + 3] = t.w;
            }

            // Shared chunk sums of squares: cs[i] = sum v[5i..5i+4]^2.
            float cs[7];
            #pragma unroll
            for (int i = 0; i < 7; ++i) {
                const float* c = v + 5 * i;
                float a = __fmul_rn(c[0], c[0]);
                a = __fmaf_rn(c[1], c[1], a);
                a = __fmaf_rn(c[2], c[2], a);
                a = __fmaf_rn(c[3], c[3], a);
                a = __fmaf_rn(c[4], c[4], a);
                cs[i] = a;
            }

            float res[4];
            #pragma unroll
            for (int j = 0; j < 4; ++j) {
                const float* w = v + STRIDE * j;

                // Exact mean: pinned-order tree sum, then recip-mult.
                const float s    = xla_tree20(w);
                const float mean = __fmul_rn(s, 0.05f);

                // sumsq from shared chunks; ss = sumsq - 2ms + 20m^2.
                const float sumsq =
                    __fadd_rn(__fadd_rn(cs[j],     cs[j + 1]),
                              __fadd_rn(cs[j + 2], cs[j + 3]));
                const float ss  = __fmaf_rn(mean,
                                            __fmaf_rn(20.0f, mean, -2.0f * s),
                                            sumsq);
                const float var = fmaxf(ss, 0.0f) * (float)(1.0 / 19.0);
                const float sd  = sqrt_approx(var);

                float cv = __fdividef(sd, __fadd_rn(mean, EPS));
                res[j] = (cv != cv) ? 0.0f : cv;   // NaN -> 0
            }

            float4 o;
            o.x = res[0]; o.y = res[1]; o.z = res[2]; o.w = res[3];
            stg_cs_f4(out + (size_t)row * OUT_LEN + 4 * tid, o);
        }

        // Protect buf[stage] from being overwritten by the prefetch issued
        // at the top of the next iteration (windows overlap across threads).
        __syncthreads();
    }
}

extern "C" void kernel_launch(void* const* d_in, const int* in_sizes, int n_in,
                              void* d_out, int out_size)
{
    const float* x = (const float*)d_in[0];
    float* out = (float*)d_out;

    const int n_rows = in_sizes[0] / SEQ;   // 16384
    tscv_kernel<<<GRID, NTHREADS>>>(x, out, n_rows);
}

// round 12
// speedup vs baseline: 1.1068x; 1.1068x over previous
#include <cuda_runtime.h>
#include <cstdint>
#include <math.h>

// Fixed shapes: x = (64, 256, 4096) fp32 -> out (64, 256, 816)
#define SEQ        4096
#define MIN_W      20
#define STRIDE     5
#define OUT_LEN    816              // (4096-20)/5 + 1
#define GROUPS     204              // 4 windows per group
#define EPS        1e-8f
#define NTHREADS   256
#define ITERS      6
#define TOTAL_G    (16384 * GROUPS)           // 3,342,336 groups
#define THR_TOTAL  (TOTAL_G / ITERS)          // 557,056 threads
#define GRID_CTAS  (THR_TOTAL / NTHREADS)     // 2176 CTAs

// Exact XLA GPU warp-shuffle reduction tree for the 20-element window sum
// (lanes 20..31 carry identity 0; shfl-down 16,8,4,2,1). Bitwise-pinned:
// every add is a single rn FADD, no reassociation, no FMA. The MEAN must be
// bitwise-matched to the reference: global L2 rel_err is dominated by
// near-zero-mean windows where cv = std/(mean+eps) ~ 1e7.
__device__ __forceinline__ float xla_tree20(const float* __restrict__ v)
{
    float c0 = __fadd_rn(__fadd_rn(v[0], v[16]), v[8]);
    float c1 = __fadd_rn(__fadd_rn(v[1], v[17]), v[9]);
    float c2 = __fadd_rn(__fadd_rn(v[2], v[18]), v[10]);
    float c3 = __fadd_rn(__fadd_rn(v[3], v[19]), v[11]);
    float c4 = __fadd_rn(v[4], v[12]);
    float c5 = __fadd_rn(v[5], v[13]);
    float c6 = __fadd_rn(v[6], v[14]);
    float c7 = __fadd_rn(v[7], v[15]);
    float d0 = __fadd_rn(c0, c4);
    float d1 = __fadd_rn(c1, c5);
    float d2 = __fadd_rn(c2, c6);
    float d3 = __fadd_rn(c3, c7);
    return __fadd_rn(__fadd_rn(d0, d2), __fadd_rn(d1, d3));
}

__device__ __forceinline__ float sqrt_approx(float a)
{
    float r;
    asm("sqrt.approx.f32 %0, %1;" : "=f"(r) : "f"(a));
    return r;
}

// Load the 9 aligned float4 covering elements [20*loc, 20*loc+36) of row.
__device__ __forceinline__ void load_group(
    const float* __restrict__ x, int g, float4* __restrict__ dst)
{
    const int row = g / GROUPS;
    const int loc = g - row * GROUPS;
    const float4* __restrict__ src4 = reinterpret_cast<const float4*>(
        x + (size_t)row * SEQ + (size_t)MIN_W * loc);
    #pragma unroll
    for (int i = 0; i < 9; ++i) dst[i] = src4[i];
}

// Compute + store the 4 windows of group g from its 36 staged elements.
__device__ __forceinline__ void compute_group(
    const float4* __restrict__ v4, int g, float* __restrict__ out)
{
    const int row = g / GROUPS;
    const int loc = g - row * GROUPS;

    float v[36];
    #pragma unroll
    for (int i = 0; i < 9; ++i) {
        v[4 * i + 0] = v4[i].x;
        v[4 * i + 1] = v4[i].y;
        v[4 * i + 2] = v4[i].z;
        v[4 * i + 3] = v4[i].w;
    }

    // Shared chunk sums of squares: cs[i] = sum v[5i..5i+4]^2.
    float cs[7];
    #pragma unroll
    for (int i = 0; i < 7; ++i) {
        const float* c = v + 5 * i;
        float a = __fmul_rn(c[0], c[0]);
        a = __fmaf_rn(c[1], c[1], a);
        a = __fmaf_rn(c[2], c[2], a);
        a = __fmaf_rn(c[3], c[3], a);
        a = __fmaf_rn(c[4], c[4], a);
        cs[i] = a;
    }

    float res[4];
    #pragma unroll
    for (int j = 0; j < 4; ++j) {
        const float* w = v + STRIDE * j;

        // Exact mean: pinned-order tree sum, then recip-mult.
        const float s    = xla_tree20(w);
        const float mean = __fmul_rn(s, 0.05f);

        // sumsq from shared chunks; ss = sumsq - 2ms + 20m^2.
        const float sumsq = __fadd_rn(__fadd_rn(cs[j],     cs[j + 1]),
                                      __fadd_rn(cs[j + 2], cs[j + 3]));
        const float ss  = __fmaf_rn(mean,
                                    __fmaf_rn(20.0f, mean, -2.0f * s),
                                    sumsq);
        const float var = fmaxf(ss, 0.0f) * (float)(1.0 / 19.0);
        const float sd  = sqrt_approx(var);

        float cv = __fdividef(sd, __fadd_rn(mean, EPS));
        res[j] = (cv != cv) ? 0.0f : cv;   // NaN -> 0
    }

    float4 o;
    o.x = res[0]; o.y = res[1]; o.z = res[2]; o.w = res[3];
    *reinterpret_cast<float4*>(out + (size_t)row * OUT_LEN + 4 * loc) = o;
}

// Each thread processes 6 groups strided by THR_TOTAL, with a 2-deep
// register pipeline: the next group's 9 LDG.128 are issued BEFORE the
// current group's compute, so every warp keeps ~2.3KB of loads in flight
// during its compute phase. This removes the load/compute phase
// alternation that capped DRAM duty at ~77% in the flat variant.
__global__ __launch_bounds__(NTHREADS, 2) void tscv_kernel(
    const float* __restrict__ x,
    float*       __restrict__ out)
{
    int g = blockIdx.x * NTHREADS + threadIdx.x;   // base group

    float4 cur[9];
    load_group(x, g, cur);

    #pragma unroll
    for (int k = 0; k < ITERS; ++k) {
        float4 nxt[9];
        const int gn = g + THR_TOTAL;
        if (k + 1 < ITERS) {
            load_group(x, gn, nxt);        // fire loads for next group
        }
        compute_group(cur, g, out);        // overlaps with in-flight loads
        if (k + 1 < ITERS) {
            #pragma unroll
            for (int i = 0; i < 9; ++i) cur[i] = nxt[i];
        }
        g = gn;
    }
}

extern "C" void kernel_launch(void* const* d_in, const int* in_sizes, int n_in,
                              void* d_out, int out_size)
{
    const float* x = (const float*)d_in[0];
    float* out = (float*)d_out;

    // 2176 CTAs x 256 threads x 6 groups = 3,342,336 groups, exact cover.
    tscv_kernel<<<GRID_CTAS, NTHREADS>>>(x, out);
}

// round 14
// speedup vs baseline: 1.1919x; 1.0769x over previous
#include <cuda_runtime.h>
#include <cstdint>
#include <math.h>

// Fixed shapes: x = (64, 256, 4096) fp32 -> out (64, 256, 816)
#define SEQ      4096
#define MIN_W    20
#define STRIDE   5
#define OUT_LEN  816            // (4096-20)/5 + 1
#define GROUPS   204            // 816 / 4 windows per thread
#define EPS      1e-8f
#define NTHREADS 128            // smaller CTAs -> ~2x resident CTAs/SM ->
                                // load phases stagger across CTAs instead of
                                // colliding in the L1tex queue

// Exact XLA GPU warp-shuffle reduction tree for the 20-element window sum
// (lanes 20..31 carry identity 0; shfl-down 16,8,4,2,1). Bitwise-pinned:
// every add is a single rn FADD, no reassociation, no FMA. The MEAN must be
// bitwise-matched to the reference: global L2 rel_err is dominated by
// near-zero-mean windows where cv = std/(mean+eps) ~ 1e7.
__device__ __forceinline__ float xla_tree20(const float* __restrict__ v)
{
    float c0 = __fadd_rn(__fadd_rn(v[0], v[16]), v[8]);
    float c1 = __fadd_rn(__fadd_rn(v[1], v[17]), v[9]);
    float c2 = __fadd_rn(__fadd_rn(v[2], v[18]), v[10]);
    float c3 = __fadd_rn(__fadd_rn(v[3], v[19]), v[11]);
    float c4 = __fadd_rn(v[4], v[12]);
    float c5 = __fadd_rn(v[5], v[13]);
    float c6 = __fadd_rn(v[6], v[14]);
    float c7 = __fadd_rn(v[7], v[15]);
    float d0 = __fadd_rn(c0, c4);
    float d1 = __fadd_rn(c1, c5);
    float d2 = __fadd_rn(c2, c6);
    float d3 = __fadd_rn(c3, c7);
    return __fadd_rn(__fadd_rn(d0, d2), __fadd_rn(d1, d3));
}

__device__ __forceinline__ float sqrt_approx(float a)
{
    float r;
    asm("sqrt.approx.f32 %0, %1;" : "=f"(r) : "f"(a));
    return r;
}

// Each thread: 4 consecutive windows of one row.
//   group loc in [0,204): windows 4*loc..4*loc+3, elements [20*loc, 20*loc+36)
//   = exactly 9 aligned float4 loads; group 203 ends exactly at element 4096.
__global__ __launch_bounds__(NTHREADS) void tscv_kernel(
    const float* __restrict__ x,
    float*       __restrict__ out)
{
    const int g   = blockIdx.x * NTHREADS + threadIdx.x;
    const int row = g / GROUPS;
    const int loc = g - row * GROUPS;

    const float4* __restrict__ src4 = reinterpret_cast<const float4*>(
        x + (size_t)row * SEQ + (size_t)MIN_W * loc);

    float v[36];
    #pragma unroll
    for (int i = 0; i < 9; ++i) {
        const float4 t = src4[i];
        v[4 * i + 0] = t.x;
        v[4 * i + 1] = t.y;
        v[4 * i + 2] = t.z;
        v[4 * i + 3] = t.w;
    }

    // Shared chunk sums of squares: cs[i] = sum v[5i..5i+4]^2 (i = 0..6).
    // Window j's sumsq = chunks j..j+3. std only needs ~1e-5 relative
    // accuracy; the error budget is carried by the bitwise-exact mean.
    float cs[7];
    #pragma unroll
    for (int i = 0; i < 7; ++i) {
        const float* c = v + 5 * i;
        float a = __fmul_rn(c[0], c[0]);
        a = __fmaf_rn(c[1], c[1], a);
        a = __fmaf_rn(c[2], c[2], a);
        a = __fmaf_rn(c[3], c[3], a);
        a = __fmaf_rn(c[4], c[4], a);
        cs[i] = a;
    }

    float res[4];
    #pragma unroll
    for (int j = 0; j < 4; ++j) {
        const float* w = v + STRIDE * j;

        // Exact mean: pinned-order tree sum, then recip-mult.
        const float s    = xla_tree20(w);
        const float mean = __fmul_rn(s, 0.05f);

        // sumsq from shared chunks; sum((x-m)^2) = sumsq - 2ms + 20m^2.
        const float sumsq = __fadd_rn(__fadd_rn(cs[j],     cs[j + 1]),
                                      __fadd_rn(cs[j + 2], cs[j + 3]));
        const float ss  = __fmaf_rn(mean,
                                    __fmaf_rn(20.0f, mean, -2.0f * s),
                                    sumsq);
        const float var = fmaxf(ss, 0.0f) * (float)(1.0 / 19.0);
        const float sd  = sqrt_approx(var);

        float cv = __fdividef(sd, __fadd_rn(mean, EPS));
        res[j] = (cv != cv) ? 0.0f : cv;   // NaN -> 0 (matches jnp.where)
    }

    // 4 consecutive outputs -> one aligned 16B store.
    float4 o;
    o.x = res[0]; o.y = res[1]; o.z = res[2]; o.w = res[3];
    *reinterpret_cast<float4*>(out + (size_t)row * OUT_LEN + 4 * loc) = o;
}

extern "C" void kernel_launch(void* const* d_in, const int* in_sizes, int n_in,
                              void* d_out, int out_size)
{
    const float* x = (const float*)d_in[0];
    float* out = (float*)d_out;

    // 16384 rows * 204 groups = 3,342,336 threads = 26112 CTAs of 128.
    const int n_rows = in_sizes[0] / SEQ;
    const int n_ctas = (n_rows * GROUPS) / NTHREADS;
    tscv_kernel<<<n_ctas, NTHREADS>>>(x, out);
}